// round 7
// baseline (speedup 1.0000x reference)
#include <cuda_runtime.h>

// Sinkhorn-Knopp, 5 iterations, linear-domain scaling-vector formulation.
//
//   a_i = 1 / sum_j exp(A_ij) * b_j      (b init 1)
//   b_j = 1 / sum_i exp(A_ij) * a_i      (uses fresh a)
//   out = exp(A_ij) * a_i * b_j
//
// Mathematically identical to the reference's alternating log-space
// row/col logsumexp normalization (log_alpha == A - u_i - v_j with
// a = e^-u, b = e^-v). No max-subtraction needed: A ~ N(0,1), so all
// intermediate magnitudes are well inside fp32 range.
//
// Fused kernel: one DRAM sweep per iteration. Each CTA owns a 16-row
// tile of one 1024x1024 matrix, stages exp(A) in SMEM, computes its
// rows' a_i, then column partial sums over its 16 rows from SMEM.
// A combine kernel reduces the 64 tile-partials per column into b_j.

#define BATCH 64
#define N 1024
#define R 16                          // rows per tile
#define TILES_PER_MAT (N / R)         // 64
#define NTILES (BATCH * TILES_PER_MAT)// 4096
#define THREADS 512
#define ITERS 5

// Scratch (allocation-free: __device__ globals)
__device__ float g_a[BATCH * N];                 // 256 KB
__device__ float g_b[BATCH * N];                 // 256 KB
__device__ float g_part[(size_t)NTILES * N];     // 16 MB

__global__ __launch_bounds__(THREADS, 3)
void sinkhorn_fused_kernel(const float* __restrict__ A, int first)
{
    __shared__ float bs[N];        // current b for this matrix
    __shared__ float a_sm[R];      // fresh a for this tile's rows
    extern __shared__ float tile[];// R * N floats of exp(A), 64 KB

    const int tid  = threadIdx.x;
    const int m    = blockIdx.x / TILES_PER_MAT;
    const int t    = blockIdx.x % TILES_PER_MAT;
    const int row0 = t * R;

    // Preload b (1.0 on first iteration)
    if (first) {
        bs[tid]       = 1.0f;
        bs[tid + 512] = 1.0f;
    } else {
        bs[tid]       = g_b[m * N + tid];
        bs[tid + 512] = g_b[m * N + tid + 512];
    }
    __syncthreads();

    // ---- Phase A: warp w handles row (row0 + w). Compute
    //      r = sum_j exp(A_ij) * b_j, stage exp(A) in SMEM. ----
    const int w   = tid >> 5;      // 0..15
    const int l   = tid & 31;
    const int row = row0 + w;

    const float4* A4 =
        reinterpret_cast<const float4*>(A) + ((size_t)m * N + row) * (N / 4);
    float4*       tile4 = reinterpret_cast<float4*>(tile + w * N);
    const float4* bs4   = reinterpret_cast<const float4*>(bs);

    float acc = 0.0f;
    #pragma unroll
    for (int k = 0; k < 8; k++) {
        int c4 = k * 32 + l;               // float4 index within row
        float4 v = A4[c4];
        float4 e;
        e.x = __expf(v.x); e.y = __expf(v.y);
        e.z = __expf(v.z); e.w = __expf(v.w);
        tile4[c4] = e;
        float4 bb = bs4[c4];
        acc += e.x * bb.x + e.y * bb.y + e.z * bb.z + e.w * bb.w;
    }
    #pragma unroll
    for (int off = 16; off; off >>= 1)
        acc += __shfl_xor_sync(0xffffffffu, acc, off);
    if (l == 0) {
        float a = 1.0f / acc;
        a_sm[w] = a;
        g_a[m * N + row] = a;              // consumed by final kernel
    }
    __syncthreads();

    // ---- Phase B: column partials over this tile's 16 rows ----
    #pragma unroll
    for (int rep = 0; rep < 2; rep++) {
        int j = tid + rep * 512;
        float s = 0.0f;
        #pragma unroll
        for (int i = 0; i < R; i++)
            s += tile[i * N + j] * a_sm[i];
        g_part[(size_t)blockIdx.x * N + j] = s;
    }
}

// b_j = 1 / sum over the 64 row-tiles' partials
__global__ void sinkhorn_combine_kernel()
{
    int idx = blockIdx.x * blockDim.x + threadIdx.x;  // 0 .. BATCH*N-1
    int m = idx >> 10;
    int j = idx & (N - 1);
    const float* p = g_part + (size_t)m * TILES_PER_MAT * N + j;
    float s = 0.0f;
    #pragma unroll
    for (int t = 0; t < TILES_PER_MAT; t++)
        s += p[t * N];
    g_b[idx] = 1.0f / s;
}

// out = exp(A) * a_i * b_j   (vectorized float4)
__global__ void sinkhorn_final_kernel(const float* __restrict__ A,
                                      float* __restrict__ out)
{
    unsigned gid = blockIdx.x * blockDim.x + threadIdx.x; // 0 .. 16M-1 float4s
    int j4  = gid & 255;
    int row = (gid >> 8) & 1023;
    int m   = gid >> 18;

    float  a  = g_a[m * N + row];
    float4 bb = reinterpret_cast<const float4*>(g_b)[m * 256 + j4];
    float4 v  = reinterpret_cast<const float4*>(A)[gid];

    float4 o;
    o.x = __expf(v.x) * a * bb.x;
    o.y = __expf(v.y) * a * bb.y;
    o.z = __expf(v.z) * a * bb.z;
    o.w = __expf(v.w) * a * bb.w;
    reinterpret_cast<float4*>(out)[gid] = o;
}

extern "C" void kernel_launch(void* const* d_in, const int* in_sizes, int n_in,
                              void* d_out, int out_size)
{
    (void)in_sizes; (void)n_in; (void)out_size;
    const float* A   = (const float*)d_in[0];
    float*       out = (float*)d_out;

    // Opt in to 64 KB dynamic SMEM (idempotent; not a stream op, capture-safe)
    cudaFuncSetAttribute(sinkhorn_fused_kernel,
                         cudaFuncAttributeMaxDynamicSharedMemorySize,
                         R * N * (int)sizeof(float));

    const size_t smem = (size_t)R * N * sizeof(float);  // 64 KB
    for (int it = 0; it < ITERS; it++) {
        sinkhorn_fused_kernel<<<NTILES, THREADS, smem>>>(A, it == 0 ? 1 : 0);
        sinkhorn_combine_kernel<<<(BATCH * N) / 256, 256>>>();
    }
    // 64M elems / 4 per thread / 256 threads = 65536 blocks
    sinkhorn_final_kernel<<<65536, 256>>>(A, out);
}

// round 8
// speedup vs baseline: 1.0019x; 1.0019x over previous
#include <cuda_runtime.h>

// Sinkhorn-Knopp, 5 iterations, linear-domain scaling-vector formulation.
//
//   a_i = 1 / sum_j exp(A_ij) * b_j      (b init 1)
//   b_j = 1 / sum_i exp(A_ij) * a_i      (uses fresh a)
//   out = exp(A_ij) * a_i * b_j
//
// Mathematically identical to the reference's alternating log-space
// row/col logsumexp normalization (log_alpha == A - u_i - v_j with
// a = e^-u, b = e^-v). No max-subtraction needed: A ~ N(0,1), so all
// intermediate magnitudes are well inside fp32 range.
//
// Fused kernel: one DRAM sweep per iteration. Each CTA owns a 16-row
// tile of one 1024x1024 matrix, stages exp(A) in SMEM, computes its
// rows' a_i, then column partial sums over its 16 rows from SMEM.
// A combine kernel reduces the 64 tile-partials per column into b_j.

#define BATCH 64
#define N 1024
#define R 16                          // rows per tile
#define TILES_PER_MAT (N / R)         // 64
#define NTILES (BATCH * TILES_PER_MAT)// 4096
#define THREADS 512
#define ITERS 5

// Scratch (allocation-free: __device__ globals)
__device__ float g_a[BATCH * N];                 // 256 KB
__device__ float g_b[BATCH * N];                 // 256 KB
__device__ float g_part[(size_t)NTILES * N];     // 16 MB

__global__ __launch_bounds__(THREADS, 3)
void sinkhorn_fused_kernel(const float* __restrict__ A, int first)
{
    __shared__ float bs[N];        // current b for this matrix
    __shared__ float a_sm[R];      // fresh a for this tile's rows
    extern __shared__ float tile[];// R * N floats of exp(A), 64 KB

    const int tid  = threadIdx.x;
    const int m    = blockIdx.x / TILES_PER_MAT;
    const int t    = blockIdx.x % TILES_PER_MAT;
    const int row0 = t * R;

    // Preload b (1.0 on first iteration)
    if (first) {
        bs[tid]       = 1.0f;
        bs[tid + 512] = 1.0f;
    } else {
        bs[tid]       = g_b[m * N + tid];
        bs[tid + 512] = g_b[m * N + tid + 512];
    }
    __syncthreads();

    // ---- Phase A: warp w handles row (row0 + w). Compute
    //      r = sum_j exp(A_ij) * b_j, stage exp(A) in SMEM. ----
    const int w   = tid >> 5;      // 0..15
    const int l   = tid & 31;
    const int row = row0 + w;

    const float4* A4 =
        reinterpret_cast<const float4*>(A) + ((size_t)m * N + row) * (N / 4);
    float4*       tile4 = reinterpret_cast<float4*>(tile + w * N);
    const float4* bs4   = reinterpret_cast<const float4*>(bs);

    float acc = 0.0f;
    #pragma unroll
    for (int k = 0; k < 8; k++) {
        int c4 = k * 32 + l;               // float4 index within row
        float4 v = A4[c4];
        float4 e;
        e.x = __expf(v.x); e.y = __expf(v.y);
        e.z = __expf(v.z); e.w = __expf(v.w);
        tile4[c4] = e;
        float4 bb = bs4[c4];
        acc += e.x * bb.x + e.y * bb.y + e.z * bb.z + e.w * bb.w;
    }
    #pragma unroll
    for (int off = 16; off; off >>= 1)
        acc += __shfl_xor_sync(0xffffffffu, acc, off);
    if (l == 0) {
        float a = 1.0f / acc;
        a_sm[w] = a;
        g_a[m * N + row] = a;              // consumed by final kernel
    }
    __syncthreads();

    // ---- Phase B: column partials over this tile's 16 rows ----
    #pragma unroll
    for (int rep = 0; rep < 2; rep++) {
        int j = tid + rep * 512;
        float s = 0.0f;
        #pragma unroll
        for (int i = 0; i < R; i++)
            s += tile[i * N + j] * a_sm[i];
        g_part[(size_t)blockIdx.x * N + j] = s;
    }
}

// b_j = 1 / sum over the 64 row-tiles' partials
__global__ void sinkhorn_combine_kernel()
{
    int idx = blockIdx.x * blockDim.x + threadIdx.x;  // 0 .. BATCH*N-1
    int m = idx >> 10;
    int j = idx & (N - 1);
    const float* p = g_part + (size_t)m * TILES_PER_MAT * N + j;
    float s = 0.0f;
    #pragma unroll
    for (int t = 0; t < TILES_PER_MAT; t++)
        s += p[t * N];
    g_b[idx] = 1.0f / s;
}

// out = exp(A) * a_i * b_j   (vectorized float4)
__global__ void sinkhorn_final_kernel(const float* __restrict__ A,
                                      float* __restrict__ out)
{
    unsigned gid = blockIdx.x * blockDim.x + threadIdx.x; // 0 .. 16M-1 float4s
    int j4  = gid & 255;
    int row = (gid >> 8) & 1023;
    int m   = gid >> 18;

    float  a  = g_a[m * N + row];
    float4 bb = reinterpret_cast<const float4*>(g_b)[m * 256 + j4];
    float4 v  = reinterpret_cast<const float4*>(A)[gid];

    float4 o;
    o.x = __expf(v.x) * a * bb.x;
    o.y = __expf(v.y) * a * bb.y;
    o.z = __expf(v.z) * a * bb.z;
    o.w = __expf(v.w) * a * bb.w;
    reinterpret_cast<float4*>(out)[gid] = o;
}

extern "C" void kernel_launch(void* const* d_in, const int* in_sizes, int n_in,
                              void* d_out, int out_size)
{
    (void)in_sizes; (void)n_in; (void)out_size;
    const float* A   = (const float*)d_in[0];
    float*       out = (float*)d_out;

    // Opt in to 64 KB dynamic SMEM (idempotent; not a stream op, capture-safe)
    cudaFuncSetAttribute(sinkhorn_fused_kernel,
                         cudaFuncAttributeMaxDynamicSharedMemorySize,
                         R * N * (int)sizeof(float));

    const size_t smem = (size_t)R * N * sizeof(float);  // 64 KB
    for (int it = 0; it < ITERS; it++) {
        sinkhorn_fused_kernel<<<NTILES, THREADS, smem>>>(A, it == 0 ? 1 : 0);
        sinkhorn_combine_kernel<<<(BATCH * N) / 256, 256>>>();
    }
    // 64M elems / 4 per thread / 256 threads = 65536 blocks
    sinkhorn_final_kernel<<<65536, 256>>>(A, out);
}